// round 4
// baseline (speedup 1.0000x reference)
#include <cuda_runtime.h>

#define B_    1024
#define NE_   128
#define NMO_  128
#define NC_   32
#define D_    64

// Scratch: mo matrix (64 MB) and per-(b,c) determinants.
__device__ float g_mo[B_ * NE_ * NMO_];
__device__ float g_dets[B_ * NC_];

// ---------------------------------------------------------------------------
// packed fp32x2 FMA (Blackwell sm_103a): 2x throughput vs 3-reg FFMA
// ---------------------------------------------------------------------------
__device__ __forceinline__ float2 ffma2(float2 a, float2 b, float2 c) {
    float2 d;
    asm("fma.rn.f32x2 %0, %1, %2, %3;"
        : "=l"(reinterpret_cast<unsigned long long&>(d))
        : "l"(reinterpret_cast<unsigned long long&>(a)),
          "l"(reinterpret_cast<unsigned long long&>(b)),
          "l"(reinterpret_cast<unsigned long long&>(c)));
    return d;
}

// ---------------------------------------------------------------------------
// GEMM: mo[R][m] = sum_n x[R][n] * W[m][n],  R = b*128+e  (131072 x 128 x 128)
// Block: 256 threads, tile 64 rows x 128 cols, K chunked by 32.
// ---------------------------------------------------------------------------
__global__ __launch_bounds__(256) void gemm_kernel(const float* __restrict__ x,
                                                   const float* __restrict__ W) {
    __shared__ __align__(16) float Xs[64][33];
    __shared__ __align__(16) float Wt[32][132];

    const int tid  = threadIdx.x;
    const int row0 = blockIdx.x * 64;
    const int cg   = tid & 15;        // 16 col-groups of 8 cols
    const int rg   = tid >> 4;        // 16 row-groups of 4 rows
    const int m0   = cg * 8;

    float2 acc[4][4];
#pragma unroll
    for (int i = 0; i < 4; ++i)
#pragma unroll
        for (int p = 0; p < 4; ++p) acc[i][p] = make_float2(0.f, 0.f);

    const int rr = tid >> 5;   // 0..7
    const int nn = tid & 31;   // 0..31

    for (int ch = 0; ch < 4; ++ch) {
#pragma unroll
        for (int q = 0; q < 8; ++q)
            Xs[rr + q * 8][nn] = x[(row0 + rr + q * 8) * 128 + ch * 32 + nn];
#pragma unroll
        for (int q = 0; q < 16; ++q)
            Wt[nn][rr + q * 8] = W[(rr + q * 8) * 128 + ch * 32 + nn];
        __syncthreads();

#pragma unroll
        for (int k = 0; k < 32; ++k) {
            const float4 b0 = *reinterpret_cast<const float4*>(&Wt[k][m0]);
            const float4 b1 = *reinterpret_cast<const float4*>(&Wt[k][m0 + 4]);
            const float2 bp0 = make_float2(b0.x, b0.y);
            const float2 bp1 = make_float2(b0.z, b0.w);
            const float2 bp2 = make_float2(b1.x, b1.y);
            const float2 bp3 = make_float2(b1.z, b1.w);
#pragma unroll
            for (int i = 0; i < 4; ++i) {
                const float a  = Xs[rg * 4 + i][k];
                const float2 ap = make_float2(a, a);
                acc[i][0] = ffma2(ap, bp0, acc[i][0]);
                acc[i][1] = ffma2(ap, bp1, acc[i][1]);
                acc[i][2] = ffma2(ap, bp2, acc[i][2]);
                acc[i][3] = ffma2(ap, bp3, acc[i][3]);
            }
        }
        __syncthreads();
    }

#pragma unroll
    for (int i = 0; i < 4; ++i) {
        float* dst = &g_mo[(row0 + rg * 4 + i) * 128 + m0];
        const float4 o0 = make_float4(acc[i][0].x, acc[i][0].y, acc[i][1].x, acc[i][1].y);
        const float4 o1 = make_float4(acc[i][2].x, acc[i][2].y, acc[i][3].x, acc[i][3].y);
        *reinterpret_cast<float4*>(dst)     = o0;
        *reinterpret_cast<float4*>(dst + 4) = o1;
    }
}

// ---------------------------------------------------------------------------
// Determinant kernel: one block per (b, c). 64 threads, thread = matrix row,
// row register-resident with column-shift so pivot column is always r[0].
// Partial pivoting, sign via inversion count, pairwise pivot product.
// ---------------------------------------------------------------------------
__global__ __launch_bounds__(64, 8) void det_kernel(const int* __restrict__ cfgs) {
    __shared__ __align__(16) float sA[64][68];
    __shared__ __align__(16) float s_prow[64];
    __shared__ float s_col[64];
    __shared__ float s_pv[64];
    __shared__ int   s_perm[64];
    __shared__ int   scfg[64];
    __shared__ int   s_cnt[64];
    __shared__ float s_inv;
    __shared__ int   s_pidx;

    const int t = threadIdx.x;
    const int b = blockIdx.x >> 5;
    const int c = blockIdx.x & 31;

    scfg[t] = cfgs[c * 64 + t];
    __syncthreads();

    // Gather sub[b,c][i][j] = mo[b, cfg[i], cfg[j]] into shared, row-coop loads
    const int   colj = scfg[t];
    const float* moB = g_mo + (size_t)b * (NE_ * NMO_);
#pragma unroll 8
    for (int i = 0; i < 64; ++i) {
        sA[i][t] = moB[scfg[i] * NMO_ + colj];
    }
    __syncthreads();

    // Pull my row into registers
    float r[64];
#pragma unroll
    for (int j4 = 0; j4 < 16; ++j4) {
        const float4 v = *reinterpret_cast<const float4*>(&sA[t][j4 * 4]);
        r[j4 * 4 + 0] = v.x; r[j4 * 4 + 1] = v.y;
        r[j4 * 4 + 2] = v.z; r[j4 * 4 + 3] = v.w;
    }

    bool alive = true;

#pragma unroll
    for (int k = 0; k < 64; ++k) {
        // publish current pivot-column element
        if (alive) s_col[t] = r[0];
        __syncthreads();

        // warp 0: argmax |col| over 64 entries, plus refined reciprocal
        if (t < 32) {
            float v0 = fabsf(s_col[t]); int i0 = t;
            const float v1 = fabsf(s_col[t + 32]);
            if (v1 > v0) { v0 = v1; i0 = t + 32; }
#pragma unroll
            for (int off = 16; off > 0; off >>= 1) {
                const float vo = __shfl_down_sync(0xffffffffu, v0, off);
                const int   io = __shfl_down_sync(0xffffffffu, i0, off);
                if (vo > v0) { v0 = vo; i0 = io; }
            }
            if (t == 0) {
                const float piv = s_col[i0];
                s_pidx   = i0;
                s_pv[k]  = piv;
                s_perm[k] = i0;
                s_inv    = __frcp_rn(piv);
            }
        }
        __syncthreads();

        const int   pidx = s_pidx;
        const float inv  = s_inv;

        // pivot row: publish shifted row (prow[j] = r[j+1]), then retire
        if (t == pidx) {
#pragma unroll
            for (int j = 0; j < 63 - k; ++j) s_prow[j] = r[j + 1];
            alive = false;
            s_col[t] = 0.0f;
        }
        __syncthreads();

        // eliminate + shift: r[j] = r[j+1] - m * prow[j]   (static bounds)
        if (alive) {
            const float m = r[0] * inv;
            const float4* pr4 = reinterpret_cast<const float4*>(s_prow);
#pragma unroll
            for (int j4 = 0; j4 * 4 < 63 - k; ++j4) {
                const float4 p = pr4[j4];
                const int base = j4 * 4;
                if (base + 0 < 63 - k) r[base + 0] = fmaf(-m, p.x, r[base + 1]);
                if (base + 1 < 63 - k) r[base + 1] = fmaf(-m, p.y, r[base + 2]);
                if (base + 2 < 63 - k) r[base + 2] = fmaf(-m, p.z, r[base + 3]);
                if (base + 3 < 63 - k) r[base + 3] = fmaf(-m, p.w, r[base + 4]);
            }
        }
    }
    __syncthreads();

    // permutation parity: inversions of pivot sequence
    const int myp = s_perm[t];
    int cnt = 0;
    for (int l = t + 1; l < 64; ++l) cnt += (myp > s_perm[l]) ? 1 : 0;
    s_cnt[t] = cnt;
    __syncthreads();

    if (t < 32) {
        float p  = s_pv[t] * s_pv[t + 32];   // pairwise product (underflow-safe)
        int   ct = s_cnt[t] + s_cnt[t + 32];
#pragma unroll
        for (int off = 16; off > 0; off >>= 1) {
            p  *= __shfl_down_sync(0xffffffffu, p, off);
            ct += __shfl_down_sync(0xffffffffu, ct, off);
        }
        if (t == 0) {
            g_dets[blockIdx.x] = (ct & 1) ? -p : p;
        }
    }
}

// ---------------------------------------------------------------------------
// out[b] = sum_c det[b,c] * W_ci[c]   (deterministic, no atomics)
// ---------------------------------------------------------------------------
__global__ void reduce_kernel(const float* __restrict__ Wci, float* __restrict__ out) {
    const int b = blockIdx.x * blockDim.x + threadIdx.x;
    if (b < B_) {
        float s = 0.0f;
#pragma unroll
        for (int c = 0; c < NC_; ++c) s += g_dets[b * NC_ + c] * Wci[c];
        out[b] = s;
    }
}

extern "C" void kernel_launch(void* const* d_in, const int* in_sizes, int n_in,
                              void* d_out, int out_size) {
    const float* x       = (const float*)d_in[0];
    const float* W_mo    = (const float*)d_in[1];
    const float* W_ci    = (const float*)d_in[2];
    const int*   configs = (const int*)d_in[3];
    float*       out     = (float*)d_out;

    gemm_kernel<<<(B_ * NE_) / 64, 256>>>(x, W_mo);
    det_kernel<<<B_ * NC_, 64>>>(configs);
    reduce_kernel<<<4, 256>>>(W_ci, out);
}

// round 5
// speedup vs baseline: 1.3461x; 1.3461x over previous
#include <cuda_runtime.h>

#define B_    1024
#define NE_   128
#define NMO_  128
#define NC_   32
#define D_    64

// Scratch: mo matrix (64 MB) and per-(b,c) determinants.
__device__ float g_mo[B_ * NE_ * NMO_];
__device__ float g_dets[B_ * NC_];

// ---------------------------------------------------------------------------
// packed fp32x2 FMA (Blackwell sm_103a): 2x throughput vs 3-reg FFMA
// ---------------------------------------------------------------------------
__device__ __forceinline__ float2 ffma2(float2 a, float2 b, float2 c) {
    float2 d;
    asm("fma.rn.f32x2 %0, %1, %2, %3;"
        : "=l"(reinterpret_cast<unsigned long long&>(d))
        : "l"(reinterpret_cast<unsigned long long&>(a)),
          "l"(reinterpret_cast<unsigned long long&>(b)),
          "l"(reinterpret_cast<unsigned long long&>(c)));
    return d;
}

// ---------------------------------------------------------------------------
// GEMM: mo[R][m] = sum_n x[R][n] * W[m][n],  R = b*128+e  (131072 x 128 x 128)
// (unchanged from R4 — 164us, improve next round)
// ---------------------------------------------------------------------------
__global__ __launch_bounds__(256) void gemm_kernel(const float* __restrict__ x,
                                                   const float* __restrict__ W) {
    __shared__ __align__(16) float Xs[64][33];
    __shared__ __align__(16) float Wt[32][132];

    const int tid  = threadIdx.x;
    const int row0 = blockIdx.x * 64;
    const int cg   = tid & 15;
    const int rg   = tid >> 4;
    const int m0   = cg * 8;

    float2 acc[4][4];
#pragma unroll
    for (int i = 0; i < 4; ++i)
#pragma unroll
        for (int p = 0; p < 4; ++p) acc[i][p] = make_float2(0.f, 0.f);

    const int rr = tid >> 5;
    const int nn = tid & 31;

    for (int ch = 0; ch < 4; ++ch) {
#pragma unroll
        for (int q = 0; q < 8; ++q)
            Xs[rr + q * 8][nn] = x[(row0 + rr + q * 8) * 128 + ch * 32 + nn];
#pragma unroll
        for (int q = 0; q < 16; ++q)
            Wt[nn][rr + q * 8] = W[(rr + q * 8) * 128 + ch * 32 + nn];
        __syncthreads();

#pragma unroll
        for (int k = 0; k < 32; ++k) {
            const float4 b0 = *reinterpret_cast<const float4*>(&Wt[k][m0]);
            const float4 b1 = *reinterpret_cast<const float4*>(&Wt[k][m0 + 4]);
            const float2 bp0 = make_float2(b0.x, b0.y);
            const float2 bp1 = make_float2(b0.z, b0.w);
            const float2 bp2 = make_float2(b1.x, b1.y);
            const float2 bp3 = make_float2(b1.z, b1.w);
#pragma unroll
            for (int i = 0; i < 4; ++i) {
                const float a  = Xs[rg * 4 + i][k];
                const float2 ap = make_float2(a, a);
                acc[i][0] = ffma2(ap, bp0, acc[i][0]);
                acc[i][1] = ffma2(ap, bp1, acc[i][1]);
                acc[i][2] = ffma2(ap, bp2, acc[i][2]);
                acc[i][3] = ffma2(ap, bp3, acc[i][3]);
            }
        }
        __syncthreads();
    }

#pragma unroll
    for (int i = 0; i < 4; ++i) {
        float* dst = &g_mo[(row0 + rg * 4 + i) * 128 + m0];
        const float4 o0 = make_float4(acc[i][0].x, acc[i][0].y, acc[i][1].x, acc[i][1].y);
        const float4 o1 = make_float4(acc[i][2].x, acc[i][2].y, acc[i][3].x, acc[i][3].y);
        *reinterpret_cast<float4*>(dst)     = o0;
        *reinterpret_cast<float4*>(dst + 4) = o1;
    }
}

// ---------------------------------------------------------------------------
// Determinant v2: ONE WARP PER MATRIX. Lane owns rows (lane, lane+32), each
// row as 32 aligned float2 pairs -> fma.rn.f32x2 updates. Pivot argmax via
// REDUX.SYNC.MAX on fabs bit patterns; pivot row staged through a 256B
// per-warp smem buffer; only __syncwarp, no block barriers.
// ---------------------------------------------------------------------------
__global__ __launch_bounds__(128, 3) void det2_kernel(const int* __restrict__ cfgs) {
    __shared__ __align__(16) float2 s_pr[4][32];
    __shared__ int s_cfg[4][64];
    __shared__ int s_step[4][64];

    const int lane = threadIdx.x & 31;
    const int w    = threadIdx.x >> 5;
    const int id   = blockIdx.x * 4 + w;   // matrix id = b*32 + c
    const int b    = id >> 5;
    const int c    = id & 31;

    s_cfg[w][lane]      = cfgs[c * 64 + lane];
    s_cfg[w][lane + 32] = cfgs[c * 64 + lane + 32];
    __syncwarp();

    const float* base = g_mo + (size_t)b * (NE_ * NMO_);
    const float* pA = base + s_cfg[w][lane]      * NMO_;
    const float* pB = base + s_cfg[w][lane + 32] * NMO_;

    // Gather the 64x64 submatrix: rows lane and lane+32, columns cfg[j]
    float2 a[32], bb[32];
#pragma unroll
    for (int j2 = 0; j2 < 32; ++j2) {
        const int c0 = s_cfg[w][2 * j2];
        const int c1 = s_cfg[w][2 * j2 + 1];
        a[j2]  = make_float2(__ldg(pA + c0), __ldg(pA + c1));
        bb[j2] = make_float2(__ldg(pB + c0), __ldg(pB + c1));
    }

    bool  aliveA = true, aliveB = true;
    float pvA = 1.f, pvB = 1.f;
    int   stepA = 0, stepB = 0;

#pragma unroll
    for (int k = 0; k < 64; ++k) {
        const int  kc  = k >> 1;
        const bool odd = (k & 1) != 0;

        const float colA = odd ? a[kc].y  : a[kc].x;
        const float colB = odd ? bb[kc].y : bb[kc].x;

        // candidates: |value| for alive rows (bit pattern of non-neg float is
        // order-isomorphic -> integer max works)
        const float cA = aliveA ? fabsf(colA) : 0.f;
        const float cB = aliveB ? fabsf(colB) : 0.f;
        const unsigned bits = __float_as_uint(fmaxf(cA, cB));

        const unsigned vmax = __reduce_max_sync(0xffffffffu, bits);
        const unsigned msk  = __ballot_sync(0xffffffffu, bits == vmax);
        const int pl = __ffs(msk) - 1;

        const bool rbMine = (cB > cA);                  // which of MY rows won
        const int  rb  = __shfl_sync(0xffffffffu, (int)rbMine, pl);
        const float piv = __shfl_sync(0xffffffffu, rbMine ? colB : colA, pl);
        const float inv = (piv != 0.f) ? __frcp_rn(piv) : 0.f;

        // retire pivot row (before computing multipliers -> its m becomes 0)
        if (lane == pl) {
            if (rbMine) { aliveB = false; pvB = piv; stepB = k; }
            else        { aliveA = false; pvA = piv; stepA = k; }
        }

        // pivot lane publishes its row's remaining pairs (rb is warp-uniform)
        if (lane == pl) {
            if (rb) {
#pragma unroll
                for (int jp = kc; jp < 32; ++jp) s_pr[w][jp] = bb[jp];
            } else {
#pragma unroll
                for (int jp = kc; jp < 32; ++jp) s_pr[w][jp] = a[jp];
            }
        }
        __syncwarp();

        const float mA = aliveA ? colA * inv : 0.f;
        const float mB = aliveB ? colB * inv : 0.f;
        const float2 nA = make_float2(-mA, -mA);
        const float2 nB = make_float2(-mB, -mB);

        if (!odd) {   // head scalar: column k+1 lives in pair kc, .y slot
            const float ph = s_pr[w][kc].y;
            a[kc].y  = fmaf(-mA, ph, a[kc].y);
            bb[kc].y = fmaf(-mB, ph, bb[kc].y);
        }
#pragma unroll
        for (int jp = kc + 1; jp < 32; ++jp) {
            const float2 p = s_pr[w][jp];
            a[jp]  = ffma2(nA, p, a[jp]);
            bb[jp] = ffma2(nB, p, bb[jp]);
        }
        __syncwarp();   // protect s_pr before next step's overwrite
    }

    // ---- sign: inversion count of inverse permutation (same parity) ----
    s_step[w][lane]      = stepA;
    s_step[w][lane + 32] = stepB;
    __syncwarp();

    unsigned inv_cnt = 0;
    for (int i = lane + 1; i < 64; ++i)  inv_cnt += (stepA > s_step[w][i]);
    for (int i = lane + 33; i < 64; ++i) inv_cnt += (stepB > s_step[w][i]);
    const unsigned tot = __reduce_add_sync(0xffffffffu, inv_cnt);

    // ---- determinant: pairwise tree product of the 64 pivots ----
    float p = pvA * pvB;
#pragma unroll
    for (int off = 16; off; off >>= 1)
        p *= __shfl_xor_sync(0xffffffffu, p, off);

    if (lane == 0) g_dets[id] = (tot & 1) ? -p : p;
}

// ---------------------------------------------------------------------------
// out[b] = sum_c det[b,c] * W_ci[c]   (deterministic, no atomics)
// ---------------------------------------------------------------------------
__global__ void reduce_kernel(const float* __restrict__ Wci, float* __restrict__ out) {
    const int b = blockIdx.x * blockDim.x + threadIdx.x;
    if (b < B_) {
        float s = 0.0f;
#pragma unroll
        for (int c = 0; c < NC_; ++c) s += g_dets[b * NC_ + c] * Wci[c];
        out[b] = s;
    }
}

extern "C" void kernel_launch(void* const* d_in, const int* in_sizes, int n_in,
                              void* d_out, int out_size) {
    const float* x       = (const float*)d_in[0];
    const float* W_mo    = (const float*)d_in[1];
    const float* W_ci    = (const float*)d_in[2];
    const int*   configs = (const int*)d_in[3];
    float*       out     = (float*)d_out;

    gemm_kernel<<<(B_ * NE_) / 64, 256>>>(x, W_mo);
    det2_kernel<<<(B_ * NC_) / 4, 128>>>(configs);
    reduce_kernel<<<4, 256>>>(W_ci, out);
}

// round 9
// speedup vs baseline: 1.4543x; 1.0804x over previous
#include <cuda_runtime.h>

#define B_    1024
#define NE_   128
#define NMO_  128
#define NC_   32
#define D_    64

// Scratch: mo matrix (64 MB) and per-(b,c) determinants.
__device__ float g_mo[B_ * NE_ * NMO_];
__device__ float g_dets[B_ * NC_];

// ---------------------------------------------------------------------------
// packed fp32x2 FMA (Blackwell sm_103a)
// ---------------------------------------------------------------------------
__device__ __forceinline__ float2 ffma2(float2 a, float2 b, float2 c) {
    float2 d;
    asm("fma.rn.f32x2 %0, %1, %2, %3;"
        : "=l"(reinterpret_cast<unsigned long long&>(d))
        : "l"(reinterpret_cast<unsigned long long&>(a)),
          "l"(reinterpret_cast<unsigned long long&>(b)),
          "l"(reinterpret_cast<unsigned long long&>(c)));
    return d;
}

// ---------------------------------------------------------------------------
// GEMM v2: 128x128 block tile, 256 threads, 8x8 per thread.
// mo[R][m] = sum_n x[R][n] * W[m][n]
// ---------------------------------------------------------------------------
__global__ __launch_bounds__(256, 2) void gemm_kernel(const float* __restrict__ x,
                                                      const float* __restrict__ W) {
    __shared__ __align__(16) float Xs[128][33];
    __shared__ __align__(16) float Wt[32][132];

    const int tid  = threadIdx.x;
    const int row0 = blockIdx.x * 128;
    const int rg   = tid >> 4;        // 0..15 -> 8 rows each
    const int cg   = tid & 15;        // 0..15 -> 8 cols each
    const int m0   = cg * 8;
    const int rr   = tid >> 5;        // 0..7
    const int nn   = tid & 31;        // 0..31

    float2 acc[8][4];
#pragma unroll
    for (int i = 0; i < 8; ++i)
#pragma unroll
        for (int p = 0; p < 4; ++p) acc[i][p] = make_float2(0.f, 0.f);

    for (int ch = 0; ch < 4; ++ch) {
#pragma unroll
        for (int q = 0; q < 16; ++q)
            Xs[rr + q * 8][nn] = x[(size_t)(row0 + rr + q * 8) * 128 + ch * 32 + nn];
#pragma unroll
        for (int q = 0; q < 16; ++q)
            Wt[nn][rr + q * 8] = W[(rr + q * 8) * 128 + ch * 32 + nn];
        __syncthreads();

#pragma unroll
        for (int k = 0; k < 32; ++k) {
            const float4 b0 = *reinterpret_cast<const float4*>(&Wt[k][m0]);
            const float4 b1 = *reinterpret_cast<const float4*>(&Wt[k][m0 + 4]);
            float2 bp0 = make_float2(b0.x, b0.y);
            float2 bp1 = make_float2(b0.z, b0.w);
            float2 bp2 = make_float2(b1.x, b1.y);
            float2 bp3 = make_float2(b1.z, b1.w);
#pragma unroll
            for (int i = 0; i < 8; ++i) {
                const float av = Xs[rg * 8 + i][k];
                const float2 ap = make_float2(av, av);
                acc[i][0] = ffma2(ap, bp0, acc[i][0]);
                acc[i][1] = ffma2(ap, bp1, acc[i][1]);
                acc[i][2] = ffma2(ap, bp2, acc[i][2]);
                acc[i][3] = ffma2(ap, bp3, acc[i][3]);
            }
        }
        __syncthreads();
    }

#pragma unroll
    for (int i = 0; i < 8; ++i) {
        float* dst = &g_mo[(size_t)(row0 + rg * 8 + i) * 128 + m0];
        *reinterpret_cast<float4*>(dst) =
            make_float4(acc[i][0].x, acc[i][0].y, acc[i][1].x, acc[i][1].y);
        *reinterpret_cast<float4*>(dst + 4) =
            make_float4(acc[i][2].x, acc[i][2].y, acc[i][3].x, acc[i][3].y);
    }
}

// ---------------------------------------------------------------------------
// Determinant v3: one warp per matrix, lane owns rows (lane, lane+32) as
// 32 float2 pairs. The 64 elimination steps are TEMPLATE-RECURSION unrolled
// so every register-array index is compile-time constant (no local spill).
// Pivot argmax: one REDUX.MAX on packed (|v|&~63 | rb<<5 | lane).
// Pivot row double-buffered in smem -> single __syncwarp per step.
// ---------------------------------------------------------------------------
struct DetState {
    bool  aliveA, aliveB;
    float pvA, pvB;
    int   stepA, stepB;
};

template<int K>
struct DetStep {
    static __device__ __forceinline__ void run(float2 (&a)[32], float2 (&bb)[32],
                                               float2 (*s_pr)[32], DetState& st,
                                               const int lane) {
        constexpr int  kc  = K >> 1;
        constexpr bool odd = (K & 1) != 0;

        const float colA = odd ? a[kc].y  : a[kc].x;
        const float colB = odd ? bb[kc].y : bb[kc].x;

        const float cA = st.aliveA ? fabsf(colA) : 0.f;
        const float cB = st.aliveB ? fabsf(colB) : 0.f;
        const bool  rbMine = (cB > cA);
        const float cm = rbMine ? cB : cA;
        const unsigned packed = (__float_as_uint(cm) & 0xFFFFFFC0u)
                              | ((unsigned)rbMine << 5) | (unsigned)lane;

        const unsigned vmax = __reduce_max_sync(0xffffffffu, packed);
        const int  pl = (int)(vmax & 31u);
        const bool rb = (vmax >> 5) & 1u;

        const float sel = rb ? colB : colA;   // meaningful only on lane pl
        const float piv = __shfl_sync(0xffffffffu, sel, pl);
        const float inv = (piv != 0.f) ? __frcp_rn(piv) : 0.f;

        // retire pivot row before multipliers -> its m becomes 0
        if (lane == pl) {
            if (rb) { st.aliveB = false; st.pvB = piv; st.stepB = K; }
            else    { st.aliveA = false; st.pvA = piv; st.stepA = K; }
        }

        // publish pivot row's remaining pairs (static bounds)
        constexpr int jp0 = odd ? (kc + 1) : kc;
        float2* buf = s_pr[K & 1];
        if (lane == pl) {
            if (rb) {
#pragma unroll
                for (int jp = jp0; jp < 32; ++jp) buf[jp] = bb[jp];
            } else {
#pragma unroll
                for (int jp = jp0; jp < 32; ++jp) buf[jp] = a[jp];
            }
        }
        __syncwarp();

        const float mA = st.aliveA ? colA * inv : 0.f;
        const float mB = st.aliveB ? colB * inv : 0.f;
        const float2 nA = make_float2(-mA, -mA);
        const float2 nB = make_float2(-mB, -mB);

        if (!odd) {   // head scalar: column K+1 lives in pair kc, .y slot
            const float ph = buf[kc].y;
            a[kc].y  = fmaf(-mA, ph, a[kc].y);
            bb[kc].y = fmaf(-mB, ph, bb[kc].y);
        }
#pragma unroll
        for (int jp = kc + 1; jp < 32; ++jp) {
            const float2 p = buf[jp];
            a[jp]  = ffma2(nA, p, a[jp]);
            bb[jp] = ffma2(nB, p, bb[jp]);
        }
        // no trailing syncwarp: double buffer protects WAR across steps
        DetStep<K + 1>::run(a, bb, s_pr, st, lane);
    }
};

template<>
struct DetStep<64> {
    static __device__ __forceinline__ void run(float2 (&)[32], float2 (&)[32],
                                               float2 (*)[32], DetState&, int) {}
};

__global__ __launch_bounds__(128, 3) void det3_kernel(const int* __restrict__ cfgs) {
    __shared__ __align__(16) float2 s_pr[4][2][32];
    __shared__ int s_cfg[4][64];
    __shared__ int s_step[4][64];

    const int lane = threadIdx.x & 31;
    const int w    = threadIdx.x >> 5;
    const int id   = blockIdx.x * 4 + w;   // matrix id = b*32 + c
    const int b    = id >> 5;
    const int c    = id & 31;

    s_cfg[w][lane]      = cfgs[c * 64 + lane];
    s_cfg[w][lane + 32] = cfgs[c * 64 + lane + 32];
    __syncwarp();

    const float* base = g_mo + (size_t)b * (NE_ * NMO_);
    const float* pA = base + s_cfg[w][lane]      * NMO_;
    const float* pB = base + s_cfg[w][lane + 32] * NMO_;

    float2 a[32], bb[32];
#pragma unroll
    for (int j2 = 0; j2 < 32; ++j2) {
        const int c0 = s_cfg[w][2 * j2];
        const int c1 = s_cfg[w][2 * j2 + 1];
        a[j2]  = make_float2(__ldg(pA + c0), __ldg(pA + c1));
        bb[j2] = make_float2(__ldg(pB + c0), __ldg(pB + c1));
    }

    DetState st;
    st.aliveA = true; st.aliveB = true;
    st.pvA = 1.f; st.pvB = 1.f;
    st.stepA = 0;  st.stepB = 0;

    DetStep<0>::run(a, bb, s_pr[w], st, lane);

    // ---- sign: inversion count of the step permutation ----
    s_step[w][lane]      = st.stepA;
    s_step[w][lane + 32] = st.stepB;
    __syncwarp();

    unsigned inv_cnt = 0;
    for (int i = lane + 1; i < 64; ++i)  inv_cnt += (st.stepA > s_step[w][i]);
    for (int i = lane + 33; i < 64; ++i) inv_cnt += (st.stepB > s_step[w][i]);
    const unsigned tot = __reduce_add_sync(0xffffffffu, inv_cnt);

    // ---- determinant: pairwise tree product of the 64 pivots ----
    float p = st.pvA * st.pvB;
#pragma unroll
    for (int off = 16; off; off >>= 1)
        p *= __shfl_xor_sync(0xffffffffu, p, off);

    if (lane == 0) g_dets[id] = (tot & 1) ? -p : p;
}

// ---------------------------------------------------------------------------
// out[b] = sum_c det[b,c] * W_ci[c]   (deterministic, no atomics)
// ---------------------------------------------------------------------------
__global__ void reduce_kernel(const float* __restrict__ Wci, float* __restrict__ out) {
    const int b = blockIdx.x * blockDim.x + threadIdx.x;
    if (b < B_) {
        float s = 0.0f;
#pragma unroll
        for (int c = 0; c < NC_; ++c) s += g_dets[b * NC_ + c] * Wci[c];
        out[b] = s;
    }
}

extern "C" void kernel_launch(void* const* d_in, const int* in_sizes, int n_in,
                              void* d_out, int out_size) {
    const float* x       = (const float*)d_in[0];
    const float* W_mo    = (const float*)d_in[1];
    const float* W_ci    = (const float*)d_in[2];
    const int*   configs = (const int*)d_in[3];
    float*       out     = (float*)d_out;

    gemm_kernel<<<(B_ * NE_) / 128, 256>>>(x, W_mo);
    det3_kernel<<<(B_ * NC_) / 4, 128>>>(configs);
    reduce_kernel<<<4, 256>>>(W_ci, out);
}

// round 10
// speedup vs baseline: 1.4665x; 1.0084x over previous
#include <cuda_runtime.h>

#define B_    1024
#define NE_   128
#define NMO_  128
#define NC_   32
#define D_    64

// Scratch: mo matrix (64 MB) and per-(b,c) determinants.
__device__ float g_mo[B_ * NE_ * NMO_];
__device__ float g_dets[B_ * NC_];

// ---------------------------------------------------------------------------
// packed fp32x2 FMA (Blackwell sm_103a)
// ---------------------------------------------------------------------------
__device__ __forceinline__ float2 ffma2(float2 a, float2 b, float2 c) {
    float2 d;
    asm("fma.rn.f32x2 %0, %1, %2, %3;"
        : "=l"(reinterpret_cast<unsigned long long&>(d))
        : "l"(reinterpret_cast<unsigned long long&>(a)),
          "l"(reinterpret_cast<unsigned long long&>(b)),
          "l"(reinterpret_cast<unsigned long long&>(c)));
    return d;
}

// ---------------------------------------------------------------------------
// GEMM v2: 128x128 block tile, 256 threads, 8x8 per thread.
// mo[R][m] = sum_n x[R][n] * W[m][n]
// ---------------------------------------------------------------------------
__global__ __launch_bounds__(256, 2) void gemm_kernel(const float* __restrict__ x,
                                                      const float* __restrict__ W) {
    __shared__ __align__(16) float Xs[128][33];
    __shared__ __align__(16) float Wt[32][132];

    const int tid  = threadIdx.x;
    const int row0 = blockIdx.x * 128;
    const int rg   = tid >> 4;        // 0..15 -> 8 rows each
    const int cg   = tid & 15;        // 0..15 -> 8 cols each
    const int m0   = cg * 8;
    const int rr   = tid >> 5;        // 0..7
    const int nn   = tid & 31;        // 0..31

    float2 acc[8][4];
#pragma unroll
    for (int i = 0; i < 8; ++i)
#pragma unroll
        for (int p = 0; p < 4; ++p) acc[i][p] = make_float2(0.f, 0.f);

    for (int ch = 0; ch < 4; ++ch) {
#pragma unroll
        for (int q = 0; q < 16; ++q)
            Xs[rr + q * 8][nn] = x[(size_t)(row0 + rr + q * 8) * 128 + ch * 32 + nn];
#pragma unroll
        for (int q = 0; q < 16; ++q)
            Wt[nn][rr + q * 8] = W[(rr + q * 8) * 128 + ch * 32 + nn];
        __syncthreads();

#pragma unroll
        for (int k = 0; k < 32; ++k) {
            const float4 b0 = *reinterpret_cast<const float4*>(&Wt[k][m0]);
            const float4 b1 = *reinterpret_cast<const float4*>(&Wt[k][m0 + 4]);
            float2 bp0 = make_float2(b0.x, b0.y);
            float2 bp1 = make_float2(b0.z, b0.w);
            float2 bp2 = make_float2(b1.x, b1.y);
            float2 bp3 = make_float2(b1.z, b1.w);
#pragma unroll
            for (int i = 0; i < 8; ++i) {
                const float av = Xs[rg * 8 + i][k];
                const float2 ap = make_float2(av, av);
                acc[i][0] = ffma2(ap, bp0, acc[i][0]);
                acc[i][1] = ffma2(ap, bp1, acc[i][1]);
                acc[i][2] = ffma2(ap, bp2, acc[i][2]);
                acc[i][3] = ffma2(ap, bp3, acc[i][3]);
            }
        }
        __syncthreads();
    }

#pragma unroll
    for (int i = 0; i < 8; ++i) {
        float* dst = &g_mo[(size_t)(row0 + rg * 8 + i) * 128 + m0];
        *reinterpret_cast<float4*>(dst) =
            make_float4(acc[i][0].x, acc[i][0].y, acc[i][1].x, acc[i][1].y);
        *reinterpret_cast<float4*>(dst + 4) =
            make_float4(acc[i][2].x, acc[i][2].y, acc[i][3].x, acc[i][3].y);
    }
}

// ---------------------------------------------------------------------------
// Determinant v3: one warp per matrix, lane owns rows (lane, lane+32) as
// 32 float2 pairs. The 64 elimination steps are TEMPLATE-RECURSION unrolled
// so every register-array index is compile-time constant (no local spill).
// Pivot argmax: one REDUX.MAX on packed (|v|&~63 | rb<<5 | lane).
// Pivot row double-buffered in smem -> single __syncwarp per step.
// ---------------------------------------------------------------------------
struct DetState {
    bool  aliveA, aliveB;
    float pvA, pvB;
    int   stepA, stepB;
};

template<int K>
struct DetStep {
    static __device__ __forceinline__ void run(float2 (&a)[32], float2 (&bb)[32],
                                               float2 (*s_pr)[32], DetState& st,
                                               const int lane) {
        constexpr int  kc  = K >> 1;
        constexpr bool odd = (K & 1) != 0;

        const float colA = odd ? a[kc].y  : a[kc].x;
        const float colB = odd ? bb[kc].y : bb[kc].x;

        const float cA = st.aliveA ? fabsf(colA) : 0.f;
        const float cB = st.aliveB ? fabsf(colB) : 0.f;
        const bool  rbMine = (cB > cA);
        const float cm = rbMine ? cB : cA;
        const unsigned packed = (__float_as_uint(cm) & 0xFFFFFFC0u)
                              | ((unsigned)rbMine << 5) | (unsigned)lane;

        const unsigned vmax = __reduce_max_sync(0xffffffffu, packed);
        const int  pl = (int)(vmax & 31u);
        const bool rb = (vmax >> 5) & 1u;

        const float sel = rb ? colB : colA;   // meaningful only on lane pl
        const float piv = __shfl_sync(0xffffffffu, sel, pl);
        const float inv = (piv != 0.f) ? __frcp_rn(piv) : 0.f;

        // retire pivot row before multipliers -> its m becomes 0
        if (lane == pl) {
            if (rb) { st.aliveB = false; st.pvB = piv; st.stepB = K; }
            else    { st.aliveA = false; st.pvA = piv; st.stepA = K; }
        }

        // publish pivot row's remaining pairs (static bounds)
        constexpr int jp0 = odd ? (kc + 1) : kc;
        float2* buf = s_pr[K & 1];
        if (lane == pl) {
            if (rb) {
#pragma unroll
                for (int jp = jp0; jp < 32; ++jp) buf[jp] = bb[jp];
            } else {
#pragma unroll
                for (int jp = jp0; jp < 32; ++jp) buf[jp] = a[jp];
            }
        }
        __syncwarp();

        const float mA = st.aliveA ? colA * inv : 0.f;
        const float mB = st.aliveB ? colB * inv : 0.f;
        const float2 nA = make_float2(-mA, -mA);
        const float2 nB = make_float2(-mB, -mB);

        if (!odd) {   // head scalar: column K+1 lives in pair kc, .y slot
            const float ph = buf[kc].y;
            a[kc].y  = fmaf(-mA, ph, a[kc].y);
            bb[kc].y = fmaf(-mB, ph, bb[kc].y);
        }
#pragma unroll
        for (int jp = kc + 1; jp < 32; ++jp) {
            const float2 p = buf[jp];
            a[jp]  = ffma2(nA, p, a[jp]);
            bb[jp] = ffma2(nB, p, bb[jp]);
        }
        // no trailing syncwarp: double buffer protects WAR across steps
        DetStep<K + 1>::run(a, bb, s_pr, st, lane);
    }
};

template<>
struct DetStep<64> {
    static __device__ __forceinline__ void run(float2 (&)[32], float2 (&)[32],
                                               float2 (*)[32], DetState&, int) {}
};

__global__ __launch_bounds__(128, 3) void det3_kernel(const int* __restrict__ cfgs) {
    __shared__ __align__(16) float2 s_pr[4][2][32];
    __shared__ int s_cfg[4][64];
    __shared__ int s_step[4][64];

    const int lane = threadIdx.x & 31;
    const int w    = threadIdx.x >> 5;
    const int id   = blockIdx.x * 4 + w;   // matrix id = b*32 + c
    const int b    = id >> 5;
    const int c    = id & 31;

    s_cfg[w][lane]      = cfgs[c * 64 + lane];
    s_cfg[w][lane + 32] = cfgs[c * 64 + lane + 32];
    __syncwarp();

    const float* base = g_mo + (size_t)b * (NE_ * NMO_);
    const float* pA = base + s_cfg[w][lane]      * NMO_;
    const float* pB = base + s_cfg[w][lane + 32] * NMO_;

    float2 a[32], bb[32];
#pragma unroll
    for (int j2 = 0; j2 < 32; ++j2) {
        const int c0 = s_cfg[w][2 * j2];
        const int c1 = s_cfg[w][2 * j2 + 1];
        a[j2]  = make_float2(__ldg(pA + c0), __ldg(pA + c1));
        bb[j2] = make_float2(__ldg(pB + c0), __ldg(pB + c1));
    }

    DetState st;
    st.aliveA = true; st.aliveB = true;
    st.pvA = 1.f; st.pvB = 1.f;
    st.stepA = 0;  st.stepB = 0;

    DetStep<0>::run(a, bb, s_pr[w], st, lane);

    // ---- sign: inversion count of the step permutation ----
    s_step[w][lane]      = st.stepA;
    s_step[w][lane + 32] = st.stepB;
    __syncwarp();

    unsigned inv_cnt = 0;
    for (int i = lane + 1; i < 64; ++i)  inv_cnt += (st.stepA > s_step[w][i]);
    for (int i = lane + 33; i < 64; ++i) inv_cnt += (st.stepB > s_step[w][i]);
    const unsigned tot = __reduce_add_sync(0xffffffffu, inv_cnt);

    // ---- determinant: pairwise tree product of the 64 pivots ----
    float p = st.pvA * st.pvB;
#pragma unroll
    for (int off = 16; off; off >>= 1)
        p *= __shfl_xor_sync(0xffffffffu, p, off);

    if (lane == 0) g_dets[id] = (tot & 1) ? -p : p;
}

// ---------------------------------------------------------------------------
// out[b] = sum_c det[b,c] * W_ci[c]   (deterministic, no atomics)
// ---------------------------------------------------------------------------
__global__ void reduce_kernel(const float* __restrict__ Wci, float* __restrict__ out) {
    const int b = blockIdx.x * blockDim.x + threadIdx.x;
    if (b < B_) {
        float s = 0.0f;
#pragma unroll
        for (int c = 0; c < NC_; ++c) s += g_dets[b * NC_ + c] * Wci[c];
        out[b] = s;
    }
}

extern "C" void kernel_launch(void* const* d_in, const int* in_sizes, int n_in,
                              void* d_out, int out_size) {
    const float* x       = (const float*)d_in[0];
    const float* W_mo    = (const float*)d_in[1];
    const float* W_ci    = (const float*)d_in[2];
    const int*   configs = (const int*)d_in[3];
    float*       out     = (float*)d_out;

    gemm_kernel<<<(B_ * NE_) / 128, 256>>>(x, W_mo);
    det3_kernel<<<(B_ * NC_) / 4, 128>>>(configs);
    reduce_kernel<<<4, 256>>>(W_ci, out);
}